// round 11
// baseline (speedup 1.0000x reference)
#include <cuda_runtime.h>
#include <cuda_fp16.h>
#include <math.h>
#include <stdint.h>

#define BB 2
#define TT 2048
#define DM 1024
#define NQ 2688   // 4*32 + 8*64 + 16*128
#define NK 224    // 32 + 64 + 128
#define NW 28     // 4 + 8 + 16
#define NALL 2940 // NQ + NK + NW

// ---------------- device scratch (no allocation allowed) --------------------
__device__ float g_mean[BB * DM];
__device__ float g_std[BB * DM];
__device__ float g_probs[BB * TT * 3];
__device__ float g_Wp[(size_t)BB * TT * NW];
__device__ __align__(256) __half g_Qhi[(size_t)BB * TT * NQ];
__device__ __align__(256) __half g_Qlo[(size_t)BB * TT * NQ];
__device__ __align__(256) __half g_Khi[(size_t)BB * TT * NK];

// ---------------- portable PTX helpers --------------------------------------
__device__ __forceinline__ uint32_t smem_u32_of(const void* p) {
    uint32_t a;
    asm("{ .reg .u64 t; cvta.to.shared.u64 t, %1; cvt.u32.u64 %0, t; }" : "=r"(a) : "l"(p));
    return a;
}
#define CPASYNC16(s, g) \
    asm volatile("cp.async.cg.shared.global [%0], [%1], 16;" :: "r"(s), "l"(g))
#define CPCOMMIT() asm volatile("cp.async.commit_group;" ::: "memory")
#define CPWAIT0()  asm volatile("cp.async.wait_group 0;" ::: "memory")
#define CPWAIT1()  asm volatile("cp.async.wait_group 1;" ::: "memory")
#define LDSM4(r0, r1, r2, r3, addr) \
    asm volatile("ldmatrix.sync.aligned.m8n8.x4.shared.b16 {%0,%1,%2,%3}, [%4];" \
                 : "=r"(r0), "=r"(r1), "=r"(r2), "=r"(r3) : "r"(addr))
#define MMAF16(d0, d1, d2, d3, a0, a1, a2, a3, b0, b1) \
    asm volatile("mma.sync.aligned.m16n8k16.row.col.f32.f16.f16.f32 " \
                 "{%0,%1,%2,%3}, {%4,%5,%6,%7}, {%8,%9}, {%0,%1,%2,%3};" \
                 : "+f"(d0), "+f"(d1), "+f"(d2), "+f"(d3) \
                 : "r"(a0), "r"(a1), "r"(a2), "r"(a3), "r"(b0), "r"(b1))

// ---------------------------------------------------------------------------
// 1) per-(b,d) mean / unbiased std over T
// ---------------------------------------------------------------------------
__global__ void stats_kernel(const float* __restrict__ x) {
    int d = blockIdx.x * blockDim.x + threadIdx.x;
    int b = blockIdx.y;
    const float* px = x + (size_t)b * TT * DM + d;
    double s = 0.0, s2 = 0.0;
    for (int t = 0; t < TT; t++) {
        double v = (double)px[(size_t)t * DM];
        s += v; s2 += v * v;
    }
    double m = s / (double)TT;
    double var = (s2 - s * s / (double)TT) / (double)(TT - 1);
    if (var < 0.0) var = 0.0;
    g_mean[b * DM + d] = (float)m;
    g_std[b * DM + d] = (float)sqrt(var);
}

// ---------------------------------------------------------------------------
// 2) selector MLP + softmax
// ---------------------------------------------------------------------------
__global__ void selector_kernel(const float* __restrict__ x,
                                const float* __restrict__ w1, const float* __restrict__ b1,
                                const float* __restrict__ w2, const float* __restrict__ b2,
                                const float* __restrict__ w3, const float* __restrict__ b3) {
    __shared__ float feats[DM];
    __shared__ float h1[64];
    __shared__ float h2[64];
    __shared__ float lg[3];
    int row = blockIdx.x;
    int b = row / TT;
    int t = row % TT;
    int tid = threadIdx.x;
    float posv = 0.1f * ((float)t / (float)TT);

    for (int i = tid; i < DM; i += 256)
        feats[i] = x[(size_t)row * DM + i] + g_mean[b * DM + i] + g_std[b * DM + i] + posv;
    __syncthreads();

    int warp = tid >> 5, lane = tid & 31;
    for (int j = warp; j < 64; j += 8) {
        const float* wr = w1 + j * DM;
        float a = 0.f;
        for (int i = lane; i < DM; i += 32) a += feats[i] * wr[i];
        #pragma unroll
        for (int o = 16; o; o >>= 1) a += __shfl_down_sync(0xffffffffu, a, o);
        if (lane == 0) h1[j] = fmaxf(a + b1[j], 0.f);
    }
    __syncthreads();
    for (int j = warp; j < 64; j += 8) {
        const float* wr = w2 + j * 64;
        float a = h1[lane] * wr[lane] + h1[lane + 32] * wr[lane + 32];
        #pragma unroll
        for (int o = 16; o; o >>= 1) a += __shfl_down_sync(0xffffffffu, a, o);
        if (lane == 0) h2[j] = fmaxf(a + b2[j], 0.f);
    }
    __syncthreads();
    if (tid < 3) {
        float a = b3[tid];
        #pragma unroll 8
        for (int i = 0; i < 64; i++) a += h2[i] * w3[tid * 64 + i];
        lg[tid] = a;
    }
    __syncthreads();
    if (tid == 0) {
        float m = fmaxf(lg[0], fmaxf(lg[1], lg[2]));
        float e0 = expf(lg[0] - m), e1 = expf(lg[1] - m), e2 = expf(lg[2] - m);
        float inv = 1.f / (e0 + e1 + e2);
        g_probs[row * 3 + 0] = e0 * inv;
        g_probs[row * 3 + 1] = e1 * inv;
        g_probs[row * 3 + 2] = e2 * inv;
    }
}

// ---------------------------------------------------------------------------
// 3) HMMA projection GEMM with FUSED fp32 -> fp16 hi/lo conversion in the
//    loader (no separate split kernels). C[4096, 2940] = X @ W^T, 3-term.
//    Epilogue: cols [0,2688) -> Q fp16 hi/lo; [2688,2912) -> K fp16;
//    [2912,2940) -> Wp fp32.
// ---------------------------------------------------------------------------
#define PJ_AHI 0
#define PJ_ALO 18432
#define PJ_BHI 36864
#define PJ_BLO 46080
#define PJ_TOTAL 55296

__global__ void __launch_bounds__(256, 2)
proj_mma_kernel(const float* __restrict__ x,
                const float* __restrict__ qw0, const float* __restrict__ qw1,
                const float* __restrict__ qw2, const float* __restrict__ kw0,
                const float* __restrict__ kw1, const float* __restrict__ kw2,
                const float* __restrict__ ww0, const float* __restrict__ ww1,
                const float* __restrict__ ww2) {
    extern __shared__ char smem[];
    __shared__ const float* rowsrc[64];
    const uint32_t sb = smem_u32_of(smem);
    const int tid = threadIdx.x;
    const int wid = tid >> 5;
    const int lane = tid & 31;
    const int m0 = blockIdx.x * 128;
    const int n0 = blockIdx.y * 64;

    // per-row source pointers for the 9-way concatenated weight matrix
    if (tid < 64) {
        int row = n0 + tid;
        const float* src = nullptr; int lr = 0;
        if (row < 128)       { src = qw0; lr = row; }
        else if (row < 640)  { src = qw1; lr = row - 128; }
        else if (row < 2688) { src = qw2; lr = row - 640; }
        else if (row < 2720) { src = kw0; lr = row - 2688; }
        else if (row < 2784) { src = kw1; lr = row - 2720; }
        else if (row < 2912) { src = kw2; lr = row - 2784; }
        else if (row < 2916) { src = ww0; lr = row - 2912; }
        else if (row < 2924) { src = ww1; lr = row - 2916; }
        else if (row < NALL) { src = ww2; lr = row - 2924; }
        rowsrc[tid] = src ? src + (size_t)lr * DM : nullptr;
    }
    __syncthreads();

    const int wm = wid & 3;
    const int wn = wid >> 2;

    float facc[2][4][4];
    #pragma unroll
    for (int mt = 0; mt < 2; mt++)
        #pragma unroll
        for (int nt = 0; nt < 4; nt++)
            #pragma unroll
            for (int j = 0; j < 4; j++) facc[mt][nt][j] = 0.f;

    const int arow = wm * 32 + (lane & 15);
    const int acol = (lane >> 4) << 3;
    const int brow = wn * 32 + (lane & 7) + (((lane >> 4) & 1) << 3);
    const int bcol = ((lane >> 3) & 1) << 3;

    #pragma unroll 1
    for (int c = 0; c < DM / 64; c++) {
        const int k0 = c * 64;
        __syncthreads();

        // A tile: 128 rows x 64 cols fp32 -> fp16 hi/lo (2048 float4)
        #pragma unroll
        for (int l = 0; l < 8; l++) {
            int i = tid + l * 256;
            int row = i >> 4, f4 = i & 15;
            float4 v = *(const float4*)(x + (size_t)(m0 + row) * DM + k0 + f4 * 4);
            __half ha = __float2half(v.x), hb = __float2half(v.y);
            __half hc = __float2half(v.z), hd = __float2half(v.w);
            uint32_t off = row * 144 + f4 * 8;
            *(__half2*)(smem + PJ_AHI + off)     = __halves2half2(ha, hb);
            *(__half2*)(smem + PJ_AHI + off + 4) = __halves2half2(hc, hd);
            *(__half2*)(smem + PJ_ALO + off) =
                __halves2half2(__float2half(v.x - __half2float(ha)),
                               __float2half(v.y - __half2float(hb)));
            *(__half2*)(smem + PJ_ALO + off + 4) =
                __halves2half2(__float2half(v.z - __half2float(hc)),
                               __float2half(v.w - __half2float(hd)));
        }
        // B tile: 64 rows x 64 cols fp32 -> fp16 hi/lo (1024 float4)
        #pragma unroll
        for (int l = 0; l < 4; l++) {
            int i = tid + l * 256;
            int row = i >> 4, f4 = i & 15;
            const float* p = rowsrc[row];
            float4 v = p ? *(const float4*)(p + k0 + f4 * 4) : make_float4(0.f, 0.f, 0.f, 0.f);
            __half ha = __float2half(v.x), hb = __float2half(v.y);
            __half hc = __float2half(v.z), hd = __float2half(v.w);
            uint32_t off = row * 144 + f4 * 8;
            *(__half2*)(smem + PJ_BHI + off)     = __halves2half2(ha, hb);
            *(__half2*)(smem + PJ_BHI + off + 4) = __halves2half2(hc, hd);
            *(__half2*)(smem + PJ_BLO + off) =
                __halves2half2(__float2half(v.x - __half2float(ha)),
                               __float2half(v.y - __half2float(hb)));
            *(__half2*)(smem + PJ_BLO + off + 4) =
                __halves2half2(__float2half(v.z - __half2float(hc)),
                               __float2half(v.w - __half2float(hd)));
        }
        __syncthreads();

        #pragma unroll
        for (int kk = 0; kk < 4; kk++) {
            const int k16 = kk * 16;
            uint32_t ah[8], al[8], bv[8];
            uint32_t aaddr = sb + PJ_AHI + arow * 144 + (k16 + acol) * 2;
            LDSM4(ah[0], ah[1], ah[2], ah[3], aaddr);
            LDSM4(ah[4], ah[5], ah[6], ah[7], aaddr + 16 * 144);
            uint32_t laddr = aaddr + (PJ_ALO - PJ_AHI);
            LDSM4(al[0], al[1], al[2], al[3], laddr);
            LDSM4(al[4], al[5], al[6], al[7], laddr + 16 * 144);
            uint32_t baddr = sb + PJ_BHI + brow * 144 + (k16 + bcol) * 2;
            LDSM4(bv[0], bv[1], bv[2], bv[3], baddr);
            LDSM4(bv[4], bv[5], bv[6], bv[7], baddr + 16 * 144);
            #pragma unroll
            for (int mt = 0; mt < 2; mt++)
                #pragma unroll
                for (int nt = 0; nt < 4; nt++) {
                    MMAF16(facc[mt][nt][0], facc[mt][nt][1], facc[mt][nt][2], facc[mt][nt][3],
                           ah[mt * 4 + 0], ah[mt * 4 + 1], ah[mt * 4 + 2], ah[mt * 4 + 3],
                           bv[nt * 2 + 0], bv[nt * 2 + 1]);
                    MMAF16(facc[mt][nt][0], facc[mt][nt][1], facc[mt][nt][2], facc[mt][nt][3],
                           al[mt * 4 + 0], al[mt * 4 + 1], al[mt * 4 + 2], al[mt * 4 + 3],
                           bv[nt * 2 + 0], bv[nt * 2 + 1]);
                }
            uint32_t bladdr = baddr + (PJ_BLO - PJ_BHI);
            LDSM4(bv[0], bv[1], bv[2], bv[3], bladdr);
            LDSM4(bv[4], bv[5], bv[6], bv[7], bladdr + 16 * 144);
            #pragma unroll
            for (int mt = 0; mt < 2; mt++)
                #pragma unroll
                for (int nt = 0; nt < 4; nt++)
                    MMAF16(facc[mt][nt][0], facc[mt][nt][1], facc[mt][nt][2], facc[mt][nt][3],
                           ah[mt * 4 + 0], ah[mt * 4 + 1], ah[mt * 4 + 2], ah[mt * 4 + 3],
                           bv[nt * 2 + 0], bv[nt * 2 + 1]);
        }
    }

    #pragma unroll
    for (int mt = 0; mt < 2; mt++) {
        #pragma unroll
        for (int half = 0; half < 2; half++) {
            int m = m0 + wm * 32 + mt * 16 + (lane >> 2) + half * 8;
            #pragma unroll
            for (int nt = 0; nt < 4; nt++) {
                int col = n0 + wn * 32 + nt * 8 + (lane & 3) * 2;
                float v0 = facc[mt][nt][half * 2 + 0];
                float v1 = facc[mt][nt][half * 2 + 1];
                if (col < NQ) {
                    __half h0 = __float2half(v0), h1 = __float2half(v1);
                    size_t o = (size_t)m * NQ + col;
                    *(__half2*)(g_Qhi + o) = __halves2half2(h0, h1);
                    *(__half2*)(g_Qlo + o) =
                        __halves2half2(__float2half(v0 - __half2float(h0)),
                                       __float2half(v1 - __half2float(h1)));
                } else if (col < NQ + NK) {
                    size_t o = (size_t)m * NK + (col - NQ);
                    *(__half2*)(g_Khi + o) =
                        __halves2half2(__float2half(v0), __float2half(v1));
                } else if (col < NALL) {
                    *(float2*)(g_Wp + (size_t)m * NW + (col - NQ - NK)) = make_float2(v0, v1);
                }
            }
        }
    }
}

// ---------------------------------------------------------------------------
// 4) HMMA attention (fp16 2-term), 512 threads, 128x128 CTA tile.
//    16 warps in 4(m) x 4(n); warp tile 32x32. K resident (128 rows);
//    Q 3-stage cp.async pipeline over 42 chunks. (unchanged from R10)
// ---------------------------------------------------------------------------
#define SM_Q    0                    // 3 stages x (hi 18432 + lo 18432)
#define SM_KHI_ 110592               // 128 x 464B = 59392
#define SM_WPA  169984               // 128*28*4 = 14336
#define SM_TOT2 184320

__global__ void __launch_bounds__(512, 1)
attn_mma_kernel(float* __restrict__ out) {
    extern __shared__ char smem[];
    const uint32_t sb = smem_u32_of(smem);
    const int tid = threadIdx.x;
    const int wid = tid >> 5;
    const int lane = tid & 31;
    const int b = blockIdx.z;
    const int t0 = blockIdx.x * 128;
    const int s0 = blockIdx.y * 128;
    float* wp_s = (float*)(smem + SM_WPA);

    for (int idx = tid; idx < 128 * NW; idx += 512) {
        int tt = idx / NW, gh = idx % NW;
        int cfg = (gh < 4) ? 0 : (gh < 12) ? 1 : 2;
        int row = b * TT + t0 + tt;
        wp_s[tt * NW + gh] = g_probs[row * 3 + cfg] * g_Wp[(size_t)row * NW + gh];
    }

#define LOAD_QCHUNK(CN) do { \
    const size_t qb2 = (size_t)(b * TT + t0) * NQ + (size_t)(CN) * 64; \
    uint32_t stbase = sb + SM_Q + ((CN) % 3) * 36864; \
    _Pragma("unroll") for (int l = 0; l < 4; l++) { \
        int i = tid + l * 512; \
        int lo = i >> 10; int rem = i & 1023; \
        int row = rem >> 3, seg = rem & 7; \
        const __half* src = lo ? g_Qlo : g_Qhi; \
        CPASYNC16(stbase + lo * 18432 + row * 144 + seg * 16, \
                  src + qb2 + (size_t)row * NQ + seg * 8); \
    } } while (0)

    // K resident (hi only): 128 rows x 224 fp16 = 3584 float4
    {
        #pragma unroll
        for (int l = 0; l < 7; l++) {
            int i = tid + l * 512;
            int row = i / 28, c28 = i % 28;
            CPASYNC16(sb + SM_KHI_ + row * 464 + c28 * 16,
                      g_Khi + (size_t)(b * TT + s0 + row) * NK + c28 * 8);
        }
    }
    LOAD_QCHUNK(0);
    CPCOMMIT();
    LOAD_QCHUNK(1);
    CPCOMMIT();

    const int wm = wid & 3;
    const int wn = wid >> 2;

    float facc[2][4][4];
    #pragma unroll
    for (int mt = 0; mt < 2; mt++)
        #pragma unroll
        for (int nt = 0; nt < 4; nt++)
            #pragma unroll
            for (int j = 0; j < 4; j++) facc[mt][nt][j] = 0.f;

    const int arow = wm * 32 + (lane & 15);
    const int acol = (lane >> 4) << 3;
    const int brow = wn * 32 + (lane & 7) + (((lane >> 4) & 1) << 3);
    const int bcol = ((lane >> 3) & 1) << 3;

    float dacc[2][4][4];

#define ZERO_DACC() do { \
    _Pragma("unroll") for (int mt = 0; mt < 2; mt++) \
    _Pragma("unroll") for (int nt = 0; nt < 4; nt++) \
    _Pragma("unroll") for (int j = 0; j < 4; j++) dacc[mt][nt][j] = 0.f; } while (0)

#define K16STEP(ACOL0, KCOL0) do { \
    uint32_t ah[8], al[8], bv[8]; \
    uint32_t aaddr = qb + arow * 144 + ((ACOL0) + acol) * 2; \
    LDSM4(ah[0], ah[1], ah[2], ah[3], aaddr); \
    LDSM4(ah[4], ah[5], ah[6], ah[7], aaddr + 16 * 144); \
    LDSM4(al[0], al[1], al[2], al[3], aaddr + 18432); \
    LDSM4(al[4], al[5], al[6], al[7], aaddr + 18432 + 16 * 144); \
    uint32_t baddr = sb + SM_KHI_ + brow * 464 + ((KCOL0) + bcol) * 2; \
    LDSM4(bv[0], bv[1], bv[2], bv[3], baddr); \
    LDSM4(bv[4], bv[5], bv[6], bv[7], baddr + 16 * 464); \
    _Pragma("unroll") for (int mt = 0; mt < 2; mt++) \
    _Pragma("unroll") for (int nt = 0; nt < 4; nt++) { \
        MMAF16(dacc[mt][nt][0], dacc[mt][nt][1], dacc[mt][nt][2], dacc[mt][nt][3], \
               ah[mt * 4 + 0], ah[mt * 4 + 1], ah[mt * 4 + 2], ah[mt * 4 + 3], \
               bv[nt * 2 + 0], bv[nt * 2 + 1]); \
        MMAF16(dacc[mt][nt][0], dacc[mt][nt][1], dacc[mt][nt][2], dacc[mt][nt][3], \
               al[mt * 4 + 0], al[mt * 4 + 1], al[mt * 4 + 2], al[mt * 4 + 3], \
               bv[nt * 2 + 0], bv[nt * 2 + 1]); \
    } } while (0)

#define EPILOGUE(GH) do { \
    _Pragma("unroll") for (int mt = 0; mt < 2; mt++) { \
        int r0 = wm * 32 + mt * 16 + (lane >> 2); \
        float w0 = wp_s[r0 * NW + (GH)]; \
        float w1 = wp_s[(r0 + 8) * NW + (GH)]; \
        _Pragma("unroll") for (int nt = 0; nt < 4; nt++) { \
            facc[mt][nt][0] += w0 * fmaxf(dacc[mt][nt][0], 0.f); \
            facc[mt][nt][1] += w0 * fmaxf(dacc[mt][nt][1], 0.f); \
            facc[mt][nt][2] += w1 * fmaxf(dacc[mt][nt][2], 0.f); \
            facc[mt][nt][3] += w1 * fmaxf(dacc[mt][nt][3], 0.f); \
        } \
    } } while (0)

    #pragma unroll 1
    for (int c = 0; c < 42; c++) {
        if (c >= 40) { CPWAIT0(); } else { CPWAIT1(); }
        __syncthreads();
        if (c + 2 < 42) { LOAD_QCHUNK(c + 2); CPCOMMIT(); }

        const uint32_t qb = sb + SM_Q + (c % 3) * 36864;
        if (c < 2) {
            #pragma unroll
            for (int h2 = 0; h2 < 2; h2++) {
                ZERO_DACC();
                K16STEP(h2 * 32 + 0,  0);
                K16STEP(h2 * 32 + 16, 16);
                EPILOGUE(c * 2 + h2);
            }
        } else if (c < 10) {
            ZERO_DACC();
            K16STEP(0,  32);
            K16STEP(16, 48);
            K16STEP(32, 64);
            K16STEP(48, 80);
            EPILOGUE(c + 2);
        } else {
            int idx = c - 10;
            int half = idx & 1;
            int kb = 96 + half * 64;
            if (!half) ZERO_DACC();
            K16STEP(0,  kb);
            K16STEP(16, kb + 16);
            K16STEP(32, kb + 32);
            K16STEP(48, kb + 48);
            if (half) EPILOGUE(12 + (idx >> 1));
        }
    }

    #pragma unroll
    for (int mt = 0; mt < 2; mt++) {
        int row = t0 + wm * 32 + mt * 16 + (lane >> 2);
        #pragma unroll
        for (int nt = 0; nt < 4; nt++) {
            int col = s0 + wn * 32 + nt * 8 + (lane & 3) * 2;
            size_t o0 = (size_t)(b * TT + row) * TT + col;
            *(float2*)(out + o0) = make_float2(facc[mt][nt][0], facc[mt][nt][1]);
            *(float2*)(out + o0 + 8 * TT) = make_float2(facc[mt][nt][2], facc[mt][nt][3]);
        }
    }
}

// ---------------------------------------------------------------------------
extern "C" void kernel_launch(void* const* d_in, const int* in_sizes, int n_in,
                              void* d_out, int out_size) {
    const float* x   = (const float*)d_in[0];
    const float* w1  = (const float*)d_in[1];
    const float* b1  = (const float*)d_in[2];
    const float* w2  = (const float*)d_in[3];
    const float* b2  = (const float*)d_in[4];
    const float* w3  = (const float*)d_in[5];
    const float* b3  = (const float*)d_in[6];
    const float* qw0 = (const float*)d_in[7];
    const float* kw0 = (const float*)d_in[8];
    const float* ww0 = (const float*)d_in[9];
    const float* qw1 = (const float*)d_in[10];
    const float* kw1 = (const float*)d_in[11];
    const float* ww1 = (const float*)d_in[12];
    const float* qw2 = (const float*)d_in[13];
    const float* kw2 = (const float*)d_in[14];
    const float* ww2 = (const float*)d_in[15];
    float* out = (float*)d_out;

    stats_kernel<<<dim3(DM / 256, BB), 256>>>(x);                       // launch 1
    selector_kernel<<<BB * TT, 256>>>(x, w1, b1, w2, b2, w3, b3);       // launch 2

    cudaFuncSetAttribute(proj_mma_kernel, cudaFuncAttributeMaxDynamicSharedMemorySize, PJ_TOTAL);
    proj_mma_kernel<<<dim3(BB * TT / 128, (NALL + 63) / 64), 256, PJ_TOTAL>>>(
        x, qw0, qw1, qw2, kw0, kw1, kw2, ww0, ww1, ww2);                // launch 3

    cudaFuncSetAttribute(attn_mma_kernel, cudaFuncAttributeMaxDynamicSharedMemorySize, SM_TOT2);
    attn_mma_kernel<<<dim3(TT / 128, TT / 128, BB), 512, SM_TOT2>>>(out); // launch 4 <- profiled
}